// round 11
// baseline (speedup 1.0000x reference)
#include <cuda_runtime.h>
#include <math.h>

#define DH 64
#define DC 3
#define HPAD 36   // floats between half-vector bases (dual-broadcast bank offset)

typedef unsigned long long ull;

// Lane-interleaved generators for the half-split ownership:
// slot (g*32 + j)*32 + l  holds  S_g[row = 4*(l&15) + (j>>3)][cols 4*qq..4*qq+3],
// qq = (l>>4)*8 + (j&7).  S = 0.5*(L - L^T).   3*32*32 float4 slots.
__device__ float4 g_skew_il[DC * 32 * 32];
// Lane-interleaved P_sp, same mapping: slot j*32 + l.  32*32 float4 slots.
__device__ float4 g_psp_il[32 * 32];
// Gram matrix of generators: [S0.S0, S0.S1, S0.S2, S1.S1, S1.S2, S2.S2]
__device__ float g_gram[6];

__global__ void build_il_kernel(const float* __restrict__ L,
                                const float* __restrict__ P) {
    int idx = blockIdx.x * blockDim.x + threadIdx.x;   // over float4 slots
    int tot = DC * 32 * 32 + 32 * 32;
    if (idx >= tot) return;
    int g, j, l;
    bool isP = (idx >= DC * 32 * 32);
    if (isP) {
        int pidx = idx - DC * 32 * 32;
        l = pidx & 31; j = (pidx >> 5) & 31; g = 0;
    } else {
        l = idx & 31; j = (idx >> 5) & 31; g = idx >> 10;
    }
    int k = l & 15, h = l >> 4;
    int row = 4 * k + (j >> 3);
    int c0  = 4 * (h * 8 + (j & 7));
    float4 v;
    if (isP) {
        v.x = P[row * DH + c0 + 0];
        v.y = P[row * DH + c0 + 1];
        v.z = P[row * DH + c0 + 2];
        v.w = P[row * DH + c0 + 3];
        g_psp_il[idx - DC * 32 * 32] = v;
    } else {
        const float* Lg = L + g * DH * DH;
        v.x = 0.5f * (Lg[row * DH + c0 + 0] - Lg[(c0 + 0) * DH + row]);
        v.y = 0.5f * (Lg[row * DH + c0 + 1] - Lg[(c0 + 1) * DH + row]);
        v.z = 0.5f * (Lg[row * DH + c0 + 2] - Lg[(c0 + 2) * DH + row]);
        v.w = 0.5f * (Lg[row * DH + c0 + 3] - Lg[(c0 + 3) * DH + row]);
        g_skew_il[idx] = v;
    }
}

__global__ void gram_kernel() {
    __shared__ float red[8][6];
    int t = threadIdx.x;   // 256 threads
    float g[6] = {0.f, 0.f, 0.f, 0.f, 0.f, 0.f};
    for (int j = t; j < 1024; j += 256) {     // 32*32 slots per generator
        float4 a = g_skew_il[j];
        float4 b = g_skew_il[1024 + j];
        float4 c = g_skew_il[2048 + j];
        g[0] += a.x*a.x + a.y*a.y + a.z*a.z + a.w*a.w;
        g[1] += a.x*b.x + a.y*b.y + a.z*b.z + a.w*b.w;
        g[2] += a.x*c.x + a.y*c.y + a.z*c.z + a.w*c.w;
        g[3] += b.x*b.x + b.y*b.y + b.z*b.z + b.w*b.w;
        g[4] += b.x*c.x + b.y*c.y + b.z*c.z + b.w*c.w;
        g[5] += c.x*c.x + c.y*c.y + c.z*c.z + c.w*c.w;
    }
    #pragma unroll
    for (int off = 16; off >= 1; off >>= 1)
        #pragma unroll
        for (int i = 0; i < 6; i++)
            g[i] += __shfl_xor_sync(0xffffffffu, g[i], off);
    if ((t & 31) == 0)
        #pragma unroll
        for (int i = 0; i < 6; i++) red[t >> 5][i] = g[i];
    __syncthreads();
    if (t < 6) {
        float s = 0.f;
        #pragma unroll
        for (int w = 0; w < 8; w++) s += red[w][t];
        g_gram[t] = s;
    }
}

// ---- packed f32x2 helpers ----
__device__ __forceinline__ ull pack2(float lo, float hi) {
    float2 t = make_float2(lo, hi);
    return *reinterpret_cast<ull*>(&t);
}
__device__ __forceinline__ float2 unpack2(ull v) {
    return *reinterpret_cast<float2*>(&v);
}
__device__ __forceinline__ void ffma2(ull& d, ull a, ull b) {
    asm("fma.rn.f32x2 %0, %1, %2, %0;" : "+l"(d) : "l"(a), "l"(b));
}
__device__ __forceinline__ ull add2(ull a, ull b) {
    ull r; asm("add.rn.f32x2 %0, %1, %2;" : "=l"(r) : "l"(a), "l"(b));
    return r;
}

// Half-split matvec: o[r] = (full row 4k+r) . v, lane reads only its 32-col
// half from smem; halves combined with one shfl per row.
__device__ __forceinline__ void matvec_hs(const ull* A, const float* vhalf,
                                          float* o)
{
    const ulonglong2* vv = reinterpret_cast<const ulonglong2*>(vhalf);
    ull acc0[4] = {0ull, 0ull, 0ull, 0ull};
    ull acc1[4] = {0ull, 0ull, 0ull, 0ull};
    #pragma unroll
    for (int q = 0; q < 8; q++) {
        ulonglong2 t = vv[q];
        #pragma unroll
        for (int r = 0; r < 4; r++) {
            ffma2(acc0[r], A[(r * 8 + q) * 2],     t.x);
            ffma2(acc1[r], A[(r * 8 + q) * 2 + 1], t.y);
        }
    }
    #pragma unroll
    for (int r = 0; r < 4; r++) {
        float2 f = unpack2(add2(acc0[r], acc1[r]));
        float pr = f.x + f.y;
        pr += __shfl_xor_sync(0xffffffffu, pr, 16);
        o[r] = pr;
    }
}

// One Chebyshev term with compile-time buffer indices.
// sv[B1]=phi_{k-1} (read), sv[BF]=phi_k (write). phi_{k-2} comes in registers.
template <int B1, int BF>
__device__ __forceinline__ void cheb_iter(
    float (*sv)[2 * HPAD], const ull* A, const float* scoef,
    float* y, float* p2, float* p1, int kk,
    int h, int off4, int physoff)
{
    float o[4];
    matvec_hs(A, &sv[B1][physoff], o);
    float cf = scoef[kk];
    float pn[4];
    #pragma unroll
    for (int r = 0; r < 4; r++) {
        pn[r] = o[r] + p2[r];          // phi_k = C*phi_{k-1} + phi_{k-2}
        y[r] = fmaf(cf, pn[r], y[r]);
        p2[r] = p1[r];
        p1[r] = pn[r];
    }
    if (h == 0)
        *reinterpret_cast<float4*>(&sv[BF][off4]) =
            make_float4(pn[0], pn[1], pn[2], pn[3]);
    __syncwarp();
}

__global__ __launch_bounds__(32, 11)
void liepe_expmv_kernel(const float* __restrict__ x,
                        const float* __restrict__ rg,
                        float* __restrict__ out)
{
    __shared__ __align__(16) float sv[2][2 * HPAD];
    __shared__ float scoef[64];

    const int l = threadIdx.x;
    const int k = l & 15;
    const int h = l >> 4;
    const int pos = blockIdx.x;
    const int physoff = h * HPAD;
    const int off4 = 4 * k + ((k >= 8) ? (HPAD - 32) : 0);

    const float r0 = __ldg(&rg[pos * DC + 0]);
    const float r1 = __ldg(&rg[pos * DC + 1]);
    const float r2 = __ldg(&rg[pos * DC + 2]);

    // ---- rho from generator Gram matrix: ||A||_F^2 = r' G r ----
    float rho;
    {
        float g0 = __ldg(&g_gram[0]), g1 = __ldg(&g_gram[1]);
        float g2 = __ldg(&g_gram[2]), g3 = __ldg(&g_gram[3]);
        float g4 = __ldg(&g_gram[4]), g5 = __ldg(&g_gram[5]);
        float F2 = r0 * r0 * g0 + r1 * r1 * g3 + r2 * r2 * g5
                 + 2.0f * (r0 * r1 * g1 + r0 * r2 * g2 + r1 * r2 * g4);
        rho = 0.335f * sqrtf(fmaxf(F2, 0.f));   // 0.25 edge * 1.34 safety
        rho = fmaxf(rho, 0.5f);
    }
    int kmax = (int)ceilf(rho) + 9;
    if (kmax > 48) kmax = 48;
    const float inv_rho = 1.0f / rho;

    // ---- Bessel coefficients J_k(rho) via Miller downward (A not yet live) ----
    {
        int K = kmax + 10;
        float jp = 0.f, jc = 1e-25f;
        float s = 0.f, c1 = 0.f, c2 = 0.f;
        for (int kk = K; kk >= 1; kk--) {
            float jm = fmaf(2.0f * (float)kk * inv_rho, jc, -jp); // J_{kk-1}
            int km1 = kk - 1;
            if (km1 == l)      c1 = jm;
            if (km1 == l + 32) c2 = jm;
            if (km1 == 0)            s += jm;
            else if ((km1 & 1) == 0) s += 2.0f * jm;
            if (fabsf(jm) > 1e24f) {
                jm *= 1e-24f; jc *= 1e-24f; s *= 1e-24f;
                c1 *= 1e-24f; c2 *= 1e-24f;
            }
            jp = jc; jc = jm;
        }
        float invs = 1.0f / s;     // J0 + 2*sum_{even>=2} J_k = 1
        scoef[l]      = ((l == 0) ? 1.0f : 2.0f) * c1 * invs;
        scoef[l + 32] = 2.0f * c2 * invs;
    }

    // ---- stage x: logical v[j] at (j<32 ? j : HPAD + j-32) ----
    sv[0][l]        = x[pos * DH + l];
    sv[0][HPAD + l] = x[pos * DH + 32 + l];
    __syncwarp();

    // ---- e = P_sp @ x : coalesced interleaved P reads, shfl-combine ----
    float e[4];
    {
        const float4* vh = reinterpret_cast<const float4*>(&sv[0][physoff]);
        float d[4] = {0.f, 0.f, 0.f, 0.f};
        #pragma unroll
        for (int j = 0; j < 32; j++) {
            float4 pv = __ldg(&g_psp_il[j * 32 + l]);
            float4 vq = vh[j & 7];
            int r = j >> 3;
            d[r] = fmaf(pv.x, vq.x, fmaf(pv.y, vq.y,
                   fmaf(pv.z, vq.z, fmaf(pv.w, vq.w, d[r]))));
        }
        #pragma unroll
        for (int r = 0; r < 4; r++) {
            d[r] += __shfl_xor_sync(0xffffffffu, d[r], 16);
            e[r] = d[r];
        }
    }
    __syncwarp();
    // phi0 := e
    if (h == 0)
        *reinterpret_cast<float4*>(&sv[0][off4]) =
            make_float4(e[0], e[1], e[2], e[3]);
    __syncwarp();

    // ---- build C = (2/rho)*A, half-split rows, coalesced reads ----
    ull A[64];    // A[(r*8+q)*2 + s]: row 4k+r, col-half h, quad q, pair s
    {
        const float cs = 2.0f * inv_rho;
        const float c0 = r0 * cs, c1f = r1 * cs, c2f = r2 * cs;
        #pragma unroll
        for (int j = 0; j < 32; j++) {
            int base = j * 32 + l;
            float4 v0 = __ldg(&g_skew_il[base]);
            float4 v1 = __ldg(&g_skew_il[1024 + base]);
            float4 v2 = __ldg(&g_skew_il[2048 + base]);
            float ax = fmaf(c2f, v2.x, fmaf(c1f, v1.x, c0 * v0.x));
            float ay = fmaf(c2f, v2.y, fmaf(c1f, v1.y, c0 * v0.y));
            float az = fmaf(c2f, v2.z, fmaf(c1f, v1.z, c0 * v0.z));
            float aw = fmaf(c2f, v2.w, fmaf(c1f, v1.w, c0 * v0.w));
            A[2 * j]     = pack2(ax, ay);
            A[2 * j + 1] = pack2(az, aw);
        }
    }

    // ---- y = coef0*phi0; phi1 = 0.5*C*phi0 -> sv[1] ----
    float y[4], p1[4], p2[4];
    {
        float cf0 = scoef[0];
        float o[4];
        matvec_hs(A, &sv[0][physoff], o);
        float cf1 = scoef[1];
        #pragma unroll
        for (int r = 0; r < 4; r++) {
            y[r]  = cf0 * e[r];
            p1[r] = 0.5f * o[r];
            p2[r] = e[r];
            y[r]  = fmaf(cf1, p1[r], y[r]);
        }
        if (h == 0)
            *reinterpret_cast<float4*>(&sv[1][off4]) =
                make_float4(p1[0], p1[1], p1[2], p1[3]);
        __syncwarp();
    }

    // ---- Chebyshev loop, unrolled by 2 with constant buffer indices ----
    {
        int kk = 2;
        while (kk <= kmax) {
            cheb_iter<1, 0>(sv, A, scoef, y, p2, p1, kk, h, off4, physoff);
            if (++kk > kmax) break;
            cheb_iter<0, 1>(sv, A, scoef, y, p2, p1, kk, h, off4, physoff);
            ++kk;
        }
    }

    // both halves hold identical y after shfl-combine; h==0 stores
    if (h == 0)
        *reinterpret_cast<float4*>(&out[pos * DH + 4 * k]) =
            make_float4(y[0], y[1], y[2], y[3]);
}

extern "C" void kernel_launch(void* const* d_in, const int* in_sizes, int n_in,
                              void* d_out, int out_size)
{
    const float* x = (const float*)d_in[0];   // [B,S,64]
    const float* r = (const float*)d_in[1];   // [B,S,3]
    const float* L = (const float*)d_in[2];   // [3,64,64]
    const float* P = (const float*)d_in[3];   // [64,64]
    float* out = (float*)d_out;

    int npos = in_sizes[0] / DH;              // B*S
    int il_total = DC * 32 * 32 + 32 * 32;    // 4096 float4 slots

    build_il_kernel<<<(il_total + 255) / 256, 256>>>(L, P);
    gram_kernel<<<1, 256>>>();
    liepe_expmv_kernel<<<npos, 32>>>(x, r, out);
}

// round 12
// speedup vs baseline: 1.0419x; 1.0419x over previous
#include <cuda_runtime.h>
#include <math.h>

#define DH 64
#define DC 3

typedef unsigned long long ull;

// Lane-interleaved generators: float4 index ((gen*2+rr)*16+q)*32 + l holds
// S_gen[row = l+32*rr][cols 4q..4q+3], S = 0.5*(L - L^T).  3*2*16*32 float4s.
__device__ float4 g_skew_il[DC * 2 * 16 * 32];
// Lane-interleaved P_sp: float4 index (rr*16+q)*32 + l holds
// Psp[row = l+32*rr][cols 4q..4q+3].
__device__ float4 g_psp_il[2 * 16 * 32];
// Gram matrix of generators: [S0.S0, S0.S1, S0.S2, S1.S1, S1.S2, S2.S2]
__device__ float g_gram[6];

__global__ void build_il_kernel(const float* __restrict__ L,
                                const float* __restrict__ P) {
    int idx = blockIdx.x * blockDim.x + threadIdx.x;
    if (idx < DC * 2 * 16 * 32) {
        int l   = idx & 31;
        int q   = (idx >> 5) & 15;
        int rr  = (idx >> 9) & 1;
        int g   = idx >> 10;
        int row = l + 32 * rr;
        float4 v;
        const float* Lg = L + g * DH * DH;
        int c0 = 4 * q;
        v.x = 0.5f * (Lg[row * DH + c0 + 0] - Lg[(c0 + 0) * DH + row]);
        v.y = 0.5f * (Lg[row * DH + c0 + 1] - Lg[(c0 + 1) * DH + row]);
        v.z = 0.5f * (Lg[row * DH + c0 + 2] - Lg[(c0 + 2) * DH + row]);
        v.w = 0.5f * (Lg[row * DH + c0 + 3] - Lg[(c0 + 3) * DH + row]);
        g_skew_il[idx] = v;
    }
    int pidx = idx - DC * 2 * 16 * 32;
    if (pidx >= 0 && pidx < 2 * 16 * 32) {
        int l   = pidx & 31;
        int q   = (pidx >> 5) & 15;
        int rr  = (pidx >> 9) & 1;
        int row = l + 32 * rr;
        const float4* pr = reinterpret_cast<const float4*>(P + row * DH);
        g_psp_il[pidx] = pr[q];
    }
}

__global__ void gram_kernel() {
    __shared__ float red[8][6];
    int t = threadIdx.x;   // 256 threads
    float g[6] = {0.f, 0.f, 0.f, 0.f, 0.f, 0.f};
    for (int j = t; j < 1024; j += 256) {
        float4 a = g_skew_il[j];
        float4 b = g_skew_il[1024 + j];
        float4 c = g_skew_il[2048 + j];
        g[0] += a.x*a.x + a.y*a.y + a.z*a.z + a.w*a.w;
        g[1] += a.x*b.x + a.y*b.y + a.z*b.z + a.w*b.w;
        g[2] += a.x*c.x + a.y*c.y + a.z*c.z + a.w*c.w;
        g[3] += b.x*b.x + b.y*b.y + b.z*b.z + b.w*b.w;
        g[4] += b.x*c.x + b.y*c.y + b.z*c.z + b.w*c.w;
        g[5] += c.x*c.x + c.y*c.y + c.z*c.z + c.w*c.w;
    }
    #pragma unroll
    for (int off = 16; off >= 1; off >>= 1)
        #pragma unroll
        for (int i = 0; i < 6; i++)
            g[i] += __shfl_xor_sync(0xffffffffu, g[i], off);
    if ((t & 31) == 0)
        #pragma unroll
        for (int i = 0; i < 6; i++) red[t >> 5][i] = g[i];
    __syncthreads();
    if (t < 6) {
        float s = 0.f;
        #pragma unroll
        for (int w = 0; w < 8; w++) s += red[w][t];
        g_gram[t] = s;
    }
}

// ---- packed f32x2 helpers ----
__device__ __forceinline__ ull pack2(float lo, float hi) {
    float2 t = make_float2(lo, hi);
    return *reinterpret_cast<ull*>(&t);
}
__device__ __forceinline__ float2 unpack2(ull v) {
    return *reinterpret_cast<float2*>(&v);
}
__device__ __forceinline__ void ffma2(ull& d, ull a, ull b) {
    asm("fma.rn.f32x2 %0, %1, %2, %0;" : "+l"(d) : "l"(a), "l"(b));
}
__device__ __forceinline__ ull add2(ull a, ull b) {
    ull r; asm("add.rn.f32x2 %0, %1, %2;" : "=l"(r) : "l"(a), "l"(b));
    return r;
}

// Full-row matvec: lane owns rows l and l+32 over all 64 columns.
__device__ __forceinline__ void matvec_fr(const ull* A0, const ull* A1,
                                          const float* v,
                                          float& o0, float& o1)
{
    const ulonglong2* vv = reinterpret_cast<const ulonglong2*>(v);
    ull a0[4] = {0ull, 0ull, 0ull, 0ull};
    ull a1[4] = {0ull, 0ull, 0ull, 0ull};
    #pragma unroll
    for (int q = 0; q < 16; q++) {
        ulonglong2 t = vv[q];
        ffma2(a0[(2 * q)     & 3], A0[2 * q],     t.x);
        ffma2(a0[(2 * q + 1) & 3], A0[2 * q + 1], t.y);
        ffma2(a1[(2 * q)     & 3], A1[2 * q],     t.x);
        ffma2(a1[(2 * q + 1) & 3], A1[2 * q + 1], t.y);
    }
    float2 f0 = unpack2(add2(add2(a0[0], a0[1]), add2(a0[2], a0[3])));
    o0 = f0.x + f0.y;
    float2 f1 = unpack2(add2(add2(a1[0], a1[1]), add2(a1[2], a1[3])));
    o1 = f1.x + f1.y;
}

// One Chebyshev term; phi_{k-2} carried in registers (p20,p21).
// sv[B1]=phi_{k-1} (read), sv[BF]=phi_k (write).
template <int B1, int BF>
__device__ __forceinline__ void cheb_iter(
    float (*sv)[DH], const ull* A0, const ull* A1, const float* scoef,
    float& y0, float& y1, float& p20, float& p21, float& p10, float& p11,
    int kk, int l)
{
    float o0, o1;
    matvec_fr(A0, A1, sv[B1], o0, o1);
    float cf = scoef[kk];
    float pn0 = o0 + p20;            // phi_k = C*phi_{k-1} + phi_{k-2}
    float pn1 = o1 + p21;
    y0 = fmaf(cf, pn0, y0);
    y1 = fmaf(cf, pn1, y1);
    p20 = p10; p21 = p11;
    p10 = pn0; p11 = pn1;
    sv[BF][l]      = pn0;            // uniform store, no divergence
    sv[BF][l + 32] = pn1;
    __syncwarp();
}

__global__ __launch_bounds__(32, 12)
void liepe_expmv_kernel(const float* __restrict__ x,
                        const float* __restrict__ rg,
                        float* __restrict__ out)
{
    __shared__ __align__(16) float sv[2][DH];
    __shared__ float scoef[64];

    const int l = threadIdx.x;
    const int pos = blockIdx.x;

    const float r0 = __ldg(&rg[pos * DC + 0]);
    const float r1 = __ldg(&rg[pos * DC + 1]);
    const float r2 = __ldg(&rg[pos * DC + 2]);

    // ---- rho from generator Gram matrix: ||A||_F^2 = r' G r ----
    float rho;
    {
        float g0 = __ldg(&g_gram[0]), g1 = __ldg(&g_gram[1]);
        float g2 = __ldg(&g_gram[2]), g3 = __ldg(&g_gram[3]);
        float g4 = __ldg(&g_gram[4]), g5 = __ldg(&g_gram[5]);
        float F2 = r0 * r0 * g0 + r1 * r1 * g3 + r2 * r2 * g5
                 + 2.0f * (r0 * r1 * g1 + r0 * r2 * g2 + r1 * r2 * g4);
        rho = 0.335f * sqrtf(fmaxf(F2, 0.f));   // 0.25 edge * 1.34 safety
        rho = fmaxf(rho, 0.5f);
    }
    int kmax = (int)ceilf(rho) + 8;
    if (kmax > 48) kmax = 48;
    const float inv_rho = 1.0f / rho;

    // ---- Bessel coefficients J_k(rho) via Miller downward (A not yet live) ----
    {
        int K = kmax + 8;
        float jp = 0.f, jc = 1e-25f;
        float s = 0.f, c1 = 0.f, c2 = 0.f;
        for (int kk = K; kk >= 1; kk--) {
            float jm = fmaf(2.0f * (float)kk * inv_rho, jc, -jp); // J_{kk-1}
            int km1 = kk - 1;
            if (km1 == l)      c1 = jm;
            if (km1 == l + 32) c2 = jm;
            if (km1 == 0)            s += jm;
            else if ((km1 & 1) == 0) s += 2.0f * jm;
            if (fabsf(jm) > 1e24f) {
                jm *= 1e-24f; jc *= 1e-24f; s *= 1e-24f;
                c1 *= 1e-24f; c2 *= 1e-24f;
            }
            jp = jc; jc = jm;
        }
        float invs = 1.0f / s;     // J0 + 2*sum_{even>=2} J_k = 1
        scoef[l]      = ((l == 0) ? 1.0f : 2.0f) * c1 * invs;
        scoef[l + 32] = 2.0f * c2 * invs;
    }

    // ---- stage x ----
    sv[0][l]      = x[pos * DH + l];
    sv[0][l + 32] = x[pos * DH + 32 + l];
    __syncwarp();

    // ---- e = P_sp @ x : interleaved (coalesced) P reads ----
    float e0, e1;
    {
        const float4* vq4 = reinterpret_cast<const float4*>(sv[0]);
        float d0 = 0.f, d1 = 0.f;
        #pragma unroll
        for (int q = 0; q < 16; q++) {
            float4 vq = vq4[q];
            float4 p0 = __ldg(&g_psp_il[(0 * 16 + q) * 32 + l]);
            float4 p1 = __ldg(&g_psp_il[(1 * 16 + q) * 32 + l]);
            d0 = fmaf(p0.x, vq.x, fmaf(p0.y, vq.y,
                 fmaf(p0.z, vq.z, fmaf(p0.w, vq.w, d0))));
            d1 = fmaf(p1.x, vq.x, fmaf(p1.y, vq.y,
                 fmaf(p1.z, vq.z, fmaf(p1.w, vq.w, d1))));
        }
        e0 = d0; e1 = d1;
    }
    __syncwarp();
    sv[0][l]      = e0;
    sv[0][l + 32] = e1;
    __syncwarp();

    // ---- build C = (2/rho)*A rows l and l+32, interleaved (coalesced) reads ----
    ull A0[32], A1[32];
    {
        const float cs = 2.0f * inv_rho;
        const float c0 = r0 * cs, c1f = r1 * cs, c2f = r2 * cs;
        #pragma unroll
        for (int rr = 0; rr < 2; rr++) {
            ull* Ad = rr ? A1 : A0;
            #pragma unroll
            for (int q = 0; q < 16; q++) {
                int base = (rr * 16 + q) * 32 + l;
                float4 v0 = __ldg(&g_skew_il[base]);
                float4 v1 = __ldg(&g_skew_il[1024 + base]);
                float4 v2 = __ldg(&g_skew_il[2048 + base]);
                float ax = fmaf(c2f, v2.x, fmaf(c1f, v1.x, c0 * v0.x));
                float ay = fmaf(c2f, v2.y, fmaf(c1f, v1.y, c0 * v0.y));
                float az = fmaf(c2f, v2.z, fmaf(c1f, v1.z, c0 * v0.z));
                float aw = fmaf(c2f, v2.w, fmaf(c1f, v1.w, c0 * v0.w));
                Ad[2 * q]     = pack2(ax, ay);
                Ad[2 * q + 1] = pack2(az, aw);
            }
        }
    }

    // ---- y = coef0*phi0; phi1 = 0.5*C*phi0 -> sv[1]; phi0 kept in regs ----
    float cf0 = scoef[0];
    float y0 = cf0 * e0, y1 = cf0 * e1;
    float p20 = e0, p21 = e1;           // phi_{k-2}
    float p10, p11;                     // phi_{k-1}
    {
        float o0, o1;
        matvec_fr(A0, A1, sv[0], o0, o1);
        float cf1 = scoef[1];
        p10 = 0.5f * o0;
        p11 = 0.5f * o1;
        y0 = fmaf(cf1, p10, y0);
        y1 = fmaf(cf1, p11, y1);
        sv[1][l]      = p10;
        sv[1][l + 32] = p11;
        __syncwarp();
    }

    // ---- Chebyshev loop, unrolled by 2 with constant buffer indices ----
    {
        int kk = 2;
        while (kk <= kmax) {
            cheb_iter<1, 0>(sv, A0, A1, scoef, y0, y1, p20, p21, p10, p11, kk, l);
            if (++kk > kmax) break;
            cheb_iter<0, 1>(sv, A0, A1, scoef, y0, y1, p20, p21, p10, p11, kk, l);
            ++kk;
        }
    }

    out[pos * DH + l]      = y0;
    out[pos * DH + l + 32] = y1;
}

extern "C" void kernel_launch(void* const* d_in, const int* in_sizes, int n_in,
                              void* d_out, int out_size)
{
    const float* x = (const float*)d_in[0];   // [B,S,64]
    const float* r = (const float*)d_in[1];   // [B,S,3]
    const float* L = (const float*)d_in[2];   // [3,64,64]
    const float* P = (const float*)d_in[3];   // [64,64]
    float* out = (float*)d_out;

    int npos = in_sizes[0] / DH;              // B*S
    int il_total = DC * 2 * 16 * 32 + 2 * 16 * 32;   // 4096 float4 slots

    build_il_kernel<<<(il_total + 255) / 256, 256>>>(L, P);
    gram_kernel<<<1, 256>>>();
    liepe_expmv_kernel<<<npos, 32>>>(x, r, out);
}